// round 3
// baseline (speedup 1.0000x reference)
#include <cuda_runtime.h>

// ---------------------------------------------------------------------------
// SiameseBrainNet: 2x (3-layer GCN + mean pool) + pairwise distance
// N=20000 nodes, E=640000 edges, D=H=512, G=64 graphs
// R3: SGEMM rewritten with named float4 registers (no address-taken local
//     arrays -> no local-memory demotion); sgemm moved to 4th launch so the
//     ncu capture lands on it.
// ---------------------------------------------------------------------------

#define NN 20000
#define EE 640000
#define DH 512
#define GG 64

// ---- scratch (device globals; no allocation allowed) ----------------------
__device__ float g_gemm[NN * DH];     // GEMM output (h = x @ W)
__device__ float g_x[NN * DH];        // aggregation output / next layer input
__device__ int   g_deg[NN];
__device__ int   g_rowptr[NN + 1];
__device__ int   g_cursor[NN];
__device__ float g_dinv[NN];
__device__ int   g_csr_src[EE];
__device__ float g_csr_norm[EE];
__device__ float g_pooled[2][GG * DH];

// ---------------------------------------------------------------------------
// CSR construction
// ---------------------------------------------------------------------------
__global__ void zero_deg_kernel() {
    int i = blockIdx.x * blockDim.x + threadIdx.x;
    if (i < NN) g_deg[i] = 0;
}

__global__ void count_deg_kernel(const int* __restrict__ dst) {
    int e = blockIdx.x * blockDim.x + threadIdx.x;
    if (e < EE) atomicAdd(&g_deg[dst[e]], 1);
}

// single-block exclusive scan of g_deg -> g_rowptr, cursor copy, and dinv
__global__ void scan_kernel() {
    __shared__ int sh[1024];
    int tid = threadIdx.x;
    const int chunk = (NN + 1023) / 1024;   // 20
    int base = tid * chunk;
    int local = 0;
    for (int j = 0; j < chunk; j++) {
        int idx = base + j;
        if (idx < NN) local += g_deg[idx];
    }
    sh[tid] = local;
    __syncthreads();
    for (int off = 1; off < 1024; off <<= 1) {
        int v = (tid >= off) ? sh[tid - off] : 0;
        __syncthreads();
        sh[tid] += v;
        __syncthreads();
    }
    int run = (tid == 0) ? 0 : sh[tid - 1];
    for (int j = 0; j < chunk; j++) {
        int idx = base + j;
        if (idx < NN) {
            int d = g_deg[idx];
            g_rowptr[idx] = run;
            g_cursor[idx] = run;
            g_dinv[idx]   = rsqrtf((float)d + 1.0f);
            run += d;
        }
    }
    if (tid == 1023) g_rowptr[NN] = sh[1023];
}

__global__ void fill_csr_kernel(const int* __restrict__ src, const int* __restrict__ dst) {
    int e = blockIdx.x * blockDim.x + threadIdx.x;
    if (e < EE) {
        int s = src[e];
        int d = dst[e];
        int pos = atomicAdd(&g_cursor[d], 1);
        g_csr_src[pos]  = s;
        g_csr_norm[pos] = g_dinv[s] * g_dinv[d];
    }
}

// ---------------------------------------------------------------------------
// SGEMM: C[M,512] = A[M,512] @ B[512,512]
// 128x128 tile, BK=16, double-buffered smem, 256 threads, 8x8/thread.
// All per-thread state in NAMED float4 registers (no local arrays).
// ---------------------------------------------------------------------------
__global__ __launch_bounds__(256, 2) void sgemm_kernel(const float* __restrict__ A,
                                                       const float* __restrict__ B,
                                                       float* __restrict__ C, int M) {
    __shared__ float As[2][16][128];   // [buf][k][m]
    __shared__ float Bs[2][16][128];   // [buf][k][n]

    const int tid = threadIdx.x;
    const int bm = blockIdx.y, bn = blockIdx.x;

    // A load: thread -> (row 0..127, 8 floats at col aCol)
    const int aRow  = tid >> 1;
    const int aCol  = (tid & 1) * 8;
    const int aRowG = bm * 128 + aRow;
    const bool aValid = (aRowG < M);
    const float* Aptr = A + (size_t)aRowG * DH + aCol;

    // B load: thread -> (row 0..15, 8 floats at col bCol)
    const int bRow = tid >> 4;
    const int bCol = (tid & 15) * 8;
    const float* Bptr = B + (size_t)bRow * DH + bn * 128 + bCol;

    const int tx = tid & 15, ty = tid >> 4;

    const float4 z4 = make_float4(0.f, 0.f, 0.f, 0.f);

    float4 c0a = z4, c0b = z4, c1a = z4, c1b = z4;
    float4 c2a = z4, c2b = z4, c3a = z4, c3b = z4;
    float4 c4a = z4, c4b = z4, c5a = z4, c5b = z4;
    float4 c6a = z4, c6b = z4, c7a = z4, c7b = z4;

    float4 pa0, pa1, pb0, pb1;

    // ---- prologue: load tile 0 ----
    pa0 = aValid ? *(const float4*)(Aptr + 0) : z4;
    pa1 = aValid ? *(const float4*)(Aptr + 4) : z4;
    pb0 = *(const float4*)(Bptr + 0);
    pb1 = *(const float4*)(Bptr + 4);

    As[0][aCol + 0][aRow] = pa0.x;
    As[0][aCol + 1][aRow] = pa0.y;
    As[0][aCol + 2][aRow] = pa0.z;
    As[0][aCol + 3][aRow] = pa0.w;
    As[0][aCol + 4][aRow] = pa1.x;
    As[0][aCol + 5][aRow] = pa1.y;
    As[0][aCol + 6][aRow] = pa1.z;
    As[0][aCol + 7][aRow] = pa1.w;
    *(float4*)&Bs[0][bRow][bCol]     = pb0;
    *(float4*)&Bs[0][bRow][bCol + 4] = pb1;
    __syncthreads();

    const int NT = DH / 16;   // 32 tiles
    int buf = 0;

#define FMA_ROW(i, av)                                                        \
    c##i##a.x += (av) * b0.x; c##i##a.y += (av) * b0.y;                       \
    c##i##a.z += (av) * b0.z; c##i##a.w += (av) * b0.w;                       \
    c##i##b.x += (av) * b1.x; c##i##b.y += (av) * b1.y;                       \
    c##i##b.z += (av) * b1.z; c##i##b.w += (av) * b1.w;

#pragma unroll 1
    for (int kt = 0; kt < NT; kt++) {
        // prefetch next tile (gmem -> regs), overlapped with compute
        if (kt + 1 < NT) {
            const size_t off = (size_t)(kt + 1) * 16;
            pa0 = aValid ? *(const float4*)(Aptr + off) : z4;
            pa1 = aValid ? *(const float4*)(Aptr + off + 4) : z4;
            pb0 = *(const float4*)(Bptr + off * DH);
            pb1 = *(const float4*)(Bptr + off * DH + 4);
        }

#pragma unroll
        for (int kk = 0; kk < 16; kk++) {
            const float4 a0 = *(const float4*)&As[buf][kk][ty * 4];
            const float4 a1 = *(const float4*)&As[buf][kk][ty * 4 + 64];
            const float4 b0 = *(const float4*)&Bs[buf][kk][tx * 4];
            const float4 b1 = *(const float4*)&Bs[buf][kk][tx * 4 + 64];
            FMA_ROW(0, a0.x) FMA_ROW(1, a0.y) FMA_ROW(2, a0.z) FMA_ROW(3, a0.w)
            FMA_ROW(4, a1.x) FMA_ROW(5, a1.y) FMA_ROW(6, a1.z) FMA_ROW(7, a1.w)
        }

        if (kt + 1 < NT) {
            const int nb = buf ^ 1;
            As[nb][aCol + 0][aRow] = pa0.x;
            As[nb][aCol + 1][aRow] = pa0.y;
            As[nb][aCol + 2][aRow] = pa0.z;
            As[nb][aCol + 3][aRow] = pa0.w;
            As[nb][aCol + 4][aRow] = pa1.x;
            As[nb][aCol + 5][aRow] = pa1.y;
            As[nb][aCol + 6][aRow] = pa1.z;
            As[nb][aCol + 7][aRow] = pa1.w;
            *(float4*)&Bs[nb][bRow][bCol]     = pb0;
            *(float4*)&Bs[nb][bRow][bCol + 4] = pb1;
            __syncthreads();
            buf = nb;
        }
    }
#undef FMA_ROW

#define STORE_ROW(i, rowexpr)                                                 \
    {                                                                         \
        int row = (rowexpr);                                                  \
        if (row < M) {                                                        \
            float* cp = &C[(size_t)row * DH + bn * 128];                      \
            *(float4*)&cp[tx * 4]      = c##i##a;                             \
            *(float4*)&cp[tx * 4 + 64] = c##i##b;                             \
        }                                                                     \
    }
    STORE_ROW(0, bm * 128 + ty * 4 + 0)
    STORE_ROW(1, bm * 128 + ty * 4 + 1)
    STORE_ROW(2, bm * 128 + ty * 4 + 2)
    STORE_ROW(3, bm * 128 + ty * 4 + 3)
    STORE_ROW(4, bm * 128 + 64 + ty * 4 + 0)
    STORE_ROW(5, bm * 128 + 64 + ty * 4 + 1)
    STORE_ROW(6, bm * 128 + 64 + ty * 4 + 2)
    STORE_ROW(7, bm * 128 + 64 + ty * 4 + 3)
#undef STORE_ROW
}

// ---------------------------------------------------------------------------
// Aggregation: out[i] = sum_{e: dst==i} norm_e * h[src_e] + h[i]*dinv[i]^2 + b
// one block (128 threads, float4 lanes) per dst node; 4 independent accums.
// ---------------------------------------------------------------------------
__global__ __launch_bounds__(128) void aggregate_kernel(const float* __restrict__ h,
                                                        const float* __restrict__ bias,
                                                        float* __restrict__ out,
                                                        int do_relu) {
    int i = blockIdx.x;
    int t = threadIdx.x;           // 0..127, handles 4 floats
    int r0 = g_rowptr[i];
    int r1 = g_rowptr[i + 1];

    float4 a0 = make_float4(0.f, 0.f, 0.f, 0.f);
    float4 a1 = a0, a2 = a0, a3 = a0;

    int e = r0;
    for (; e + 3 < r1; e += 4) {
        int   s0 = g_csr_src[e],     s1 = g_csr_src[e + 1];
        int   s2 = g_csr_src[e + 2], s3 = g_csr_src[e + 3];
        float w0 = g_csr_norm[e],    w1 = g_csr_norm[e + 1];
        float w2 = g_csr_norm[e + 2], w3 = g_csr_norm[e + 3];
        float4 v0 = *(const float4*)&h[(size_t)s0 * DH + t * 4];
        float4 v1 = *(const float4*)&h[(size_t)s1 * DH + t * 4];
        float4 v2 = *(const float4*)&h[(size_t)s2 * DH + t * 4];
        float4 v3 = *(const float4*)&h[(size_t)s3 * DH + t * 4];
        a0.x += w0 * v0.x; a0.y += w0 * v0.y; a0.z += w0 * v0.z; a0.w += w0 * v0.w;
        a1.x += w1 * v1.x; a1.y += w1 * v1.y; a1.z += w1 * v1.z; a1.w += w1 * v1.w;
        a2.x += w2 * v2.x; a2.y += w2 * v2.y; a2.z += w2 * v2.z; a2.w += w2 * v2.w;
        a3.x += w3 * v3.x; a3.y += w3 * v3.y; a3.z += w3 * v3.z; a3.w += w3 * v3.w;
    }
    for (; e < r1; e++) {
        int   s = g_csr_src[e];
        float w = g_csr_norm[e];
        float4 v = *(const float4*)&h[(size_t)s * DH + t * 4];
        a0.x += w * v.x; a0.y += w * v.y; a0.z += w * v.z; a0.w += w * v.w;
    }

    float4 acc;
    acc.x = (a0.x + a1.x) + (a2.x + a3.x);
    acc.y = (a0.y + a1.y) + (a2.y + a3.y);
    acc.z = (a0.z + a1.z) + (a2.z + a3.z);
    acc.w = (a0.w + a1.w) + (a2.w + a3.w);

    float d = g_dinv[i];
    float w2 = d * d;
    float4 vs = *(const float4*)&h[(size_t)i * DH + t * 4];
    float4 b4 = *(const float4*)&bias[t * 4];
    acc.x += w2 * vs.x + b4.x;
    acc.y += w2 * vs.y + b4.y;
    acc.z += w2 * vs.z + b4.z;
    acc.w += w2 * vs.w + b4.w;
    if (do_relu) {
        acc.x = fmaxf(acc.x, 0.f); acc.y = fmaxf(acc.y, 0.f);
        acc.z = fmaxf(acc.z, 0.f); acc.w = fmaxf(acc.w, 0.f);
    }
    *(float4*)&out[(size_t)i * DH + t * 4] = acc;
}

// ---------------------------------------------------------------------------
// Mean pool per graph (batch is sorted -> binary search the node range)
// ---------------------------------------------------------------------------
__global__ __launch_bounds__(128) void pool_kernel(const float* __restrict__ h,
                                                   const int* __restrict__ batch,
                                                   int enc) {
    int g = blockIdx.x;
    int t = threadIdx.x;

    int lo = 0, hi = NN;
    while (lo < hi) { int m = (lo + hi) >> 1; if (batch[m] < g) lo = m + 1; else hi = m; }
    int start = lo;
    lo = start; hi = NN;
    while (lo < hi) { int m = (lo + hi) >> 1; if (batch[m] < g + 1) lo = m + 1; else hi = m; }
    int end = lo;

    float4 a0 = make_float4(0.f, 0.f, 0.f, 0.f);
    float4 a1 = a0;
    int r = start;
    for (; r + 1 < end; r += 2) {
        float4 v0 = *(const float4*)&h[(size_t)r * DH + t * 4];
        float4 v1 = *(const float4*)&h[(size_t)(r + 1) * DH + t * 4];
        a0.x += v0.x; a0.y += v0.y; a0.z += v0.z; a0.w += v0.w;
        a1.x += v1.x; a1.y += v1.y; a1.z += v1.z; a1.w += v1.w;
    }
    if (r < end) {
        float4 v = *(const float4*)&h[(size_t)r * DH + t * 4];
        a0.x += v.x; a0.y += v.y; a0.z += v.z; a0.w += v.w;
    }
    float inv = 1.0f / fmaxf((float)(end - start), 1.0f);
    float4 acc;
    acc.x = (a0.x + a1.x) * inv;
    acc.y = (a0.y + a1.y) * inv;
    acc.z = (a0.z + a1.z) * inv;
    acc.w = (a0.w + a1.w) * inv;
    *(float4*)&g_pooled[enc][g * DH + t * 4] = acc;
}

// ---------------------------------------------------------------------------
// Final pairwise distance: out[g] = || pooled_a[g] - pooled_b[g] + 1e-6 ||_2
// ---------------------------------------------------------------------------
__global__ __launch_bounds__(128) void dist_kernel(float* __restrict__ out) {
    int g = blockIdx.x;
    int t = threadIdx.x;
    const float* pa = &g_pooled[0][g * DH];
    const float* pb = &g_pooled[1][g * DH];
    float4 a = *(const float4*)&pa[t * 4];
    float4 b = *(const float4*)&pb[t * 4];
    float dx = a.x - b.x + 1e-6f;
    float dy = a.y - b.y + 1e-6f;
    float dz = a.z - b.z + 1e-6f;
    float dw = a.w - b.w + 1e-6f;
    float s = dx * dx + dy * dy + dz * dz + dw * dw;

    __shared__ float red[128];
    red[t] = s;
    __syncthreads();
    for (int off = 64; off > 0; off >>= 1) {
        if (t < off) red[t] += red[t + off];
        __syncthreads();
    }
    if (t == 0) out[g] = sqrtf(red[0]);
}

// ---------------------------------------------------------------------------
// launch
// ---------------------------------------------------------------------------
extern "C" void kernel_launch(void* const* d_in, const int* in_sizes, int n_in,
                              void* d_out, int out_size) {
    const float* x_a     = (const float*)d_in[0];
    const int*   ei_a    = (const int*)  d_in[1];
    const int*   batch_a = (const int*)  d_in[2];
    const float* x_b     = (const float*)d_in[3];
    const int*   ei_b    = (const int*)  d_in[4];
    const int*   batch_b = (const int*)  d_in[5];
    const float* W1 = (const float*)d_in[6];
    const float* b1 = (const float*)d_in[7];
    const float* W2 = (const float*)d_in[8];
    const float* b2 = (const float*)d_in[9];
    const float* W3 = (const float*)d_in[10];
    const float* b3 = (const float*)d_in[11];
    float* out = (float*)d_out;

    const dim3 gemm_grid(DH / 128, (NN + 127) / 128);   // (4, 157)
    const int  eblocks = (EE + 255) / 256;
    const int  nblocks = (NN + 255) / 256;

    for (int enc = 0; enc < 2; enc++) {
        const float* x   = enc ? x_b : x_a;
        const int*   ei  = enc ? ei_b : ei_a;
        const int*   bat = enc ? batch_b : batch_a;
        const int* src = ei;
        const int* dst = ei + EE;

        // CSR build interleaved with layer-1 GEMM (GEMM is independent of CSR;
        // placing it 4th makes it the launch the ncu capture lands on)
        zero_deg_kernel<<<nblocks, 256>>>();
        count_deg_kernel<<<eblocks, 256>>>(dst);
        scan_kernel<<<1, 1024>>>();
        sgemm_kernel<<<gemm_grid, 256>>>(x, W1, g_gemm, NN);   // 4th launch
        fill_csr_kernel<<<eblocks, 256>>>(src, dst);

        // layer 1 aggregation
        aggregate_kernel<<<NN, 128>>>(g_gemm, b1, g_x, 1);
        // layer 2
        sgemm_kernel<<<gemm_grid, 256>>>(g_x, W2, g_gemm, NN);
        aggregate_kernel<<<NN, 128>>>(g_gemm, b2, g_x, 1);
        // layer 3
        sgemm_kernel<<<gemm_grid, 256>>>(g_x, W3, g_gemm, NN);
        aggregate_kernel<<<NN, 128>>>(g_gemm, b3, g_x, 0);

        // mean pool
        pool_kernel<<<GG, 128>>>(g_x, bat, enc);
    }

    dist_kernel<<<GG, 128>>>(out);
}

// round 4
// speedup vs baseline: 1.0012x; 1.0012x over previous
#include <cuda_runtime.h>

// ---------------------------------------------------------------------------
// SiameseBrainNet: 2x (3-layer GCN + mean pool) + pairwise distance
// N=20000 nodes, E=640000 edges, D=H=512, G=64 graphs
// R4: instrumentation round. A probe aggregate (identical code/shape, real
//     CSR, h=x_a, dead output) is placed as the 4th launch so ncu lands on
//     it. zero_deg eliminated via "deg is zero on entry" invariant (scan
//     re-zeros after reading). Everything else identical to R3.
// ---------------------------------------------------------------------------

#define NN 20000
#define EE 640000
#define DH 512
#define GG 64

// ---- scratch (device globals; no allocation allowed) ----------------------
__device__ float g_gemm[NN * DH];     // GEMM output (h = x @ W)
__device__ float g_x[NN * DH];        // aggregation output / next layer input
__device__ float g_probe[NN * DH];    // dead output for the probe kernel
__device__ int   g_deg[NN];           // INVARIANT: all zero at kernel_launch entry
__device__ int   g_rowptr[NN + 1];
__device__ int   g_cursor[NN];
__device__ float g_dinv[NN];
__device__ int   g_csr_src[EE];
__device__ float g_csr_norm[EE];
__device__ float g_pooled[2][GG * DH];

// ---------------------------------------------------------------------------
// CSR construction
// ---------------------------------------------------------------------------
__global__ void count_deg_kernel(const int* __restrict__ dst) {
    int e = blockIdx.x * blockDim.x + threadIdx.x;
    if (e < EE) atomicAdd(&g_deg[dst[e]], 1);
}

// single-block exclusive scan of g_deg -> g_rowptr, cursor copy, dinv,
// and RE-ZERO g_deg (maintains the entry invariant for the next call/replay)
__global__ void scan_kernel() {
    __shared__ int sh[1024];
    int tid = threadIdx.x;
    const int chunk = (NN + 1023) / 1024;   // 20
    int base = tid * chunk;
    int local = 0;
    for (int j = 0; j < chunk; j++) {
        int idx = base + j;
        if (idx < NN) local += g_deg[idx];
    }
    sh[tid] = local;
    __syncthreads();
    for (int off = 1; off < 1024; off <<= 1) {
        int v = (tid >= off) ? sh[tid - off] : 0;
        __syncthreads();
        sh[tid] += v;
        __syncthreads();
    }
    int run = (tid == 0) ? 0 : sh[tid - 1];
    for (int j = 0; j < chunk; j++) {
        int idx = base + j;
        if (idx < NN) {
            int d = g_deg[idx];
            g_deg[idx]    = 0;                      // restore invariant
            g_rowptr[idx] = run;
            g_cursor[idx] = run;
            g_dinv[idx]   = rsqrtf((float)d + 1.0f);
            run += d;
        }
    }
    if (tid == 1023) g_rowptr[NN] = sh[1023];
}

__global__ void fill_csr_kernel(const int* __restrict__ src, const int* __restrict__ dst) {
    int e = blockIdx.x * blockDim.x + threadIdx.x;
    if (e < EE) {
        int s = src[e];
        int d = dst[e];
        int pos = atomicAdd(&g_cursor[d], 1);
        g_csr_src[pos]  = s;
        g_csr_norm[pos] = g_dinv[s] * g_dinv[d];
    }
}

// ---------------------------------------------------------------------------
// SGEMM: C[M,512] = A[M,512] @ B[512,512]  (unchanged from R3; ~386us, near
// SIMT roofline)
// ---------------------------------------------------------------------------
__global__ __launch_bounds__(256, 2) void sgemm_kernel(const float* __restrict__ A,
                                                       const float* __restrict__ B,
                                                       float* __restrict__ C, int M) {
    __shared__ float As[2][16][128];   // [buf][k][m]
    __shared__ float Bs[2][16][128];   // [buf][k][n]

    const int tid = threadIdx.x;
    const int bm = blockIdx.y, bn = blockIdx.x;

    const int aRow  = tid >> 1;
    const int aCol  = (tid & 1) * 8;
    const int aRowG = bm * 128 + aRow;
    const bool aValid = (aRowG < M);
    const float* Aptr = A + (size_t)aRowG * DH + aCol;

    const int bRow = tid >> 4;
    const int bCol = (tid & 15) * 8;
    const float* Bptr = B + (size_t)bRow * DH + bn * 128 + bCol;

    const int tx = tid & 15, ty = tid >> 4;

    const float4 z4 = make_float4(0.f, 0.f, 0.f, 0.f);

    float4 c0a = z4, c0b = z4, c1a = z4, c1b = z4;
    float4 c2a = z4, c2b = z4, c3a = z4, c3b = z4;
    float4 c4a = z4, c4b = z4, c5a = z4, c5b = z4;
    float4 c6a = z4, c6b = z4, c7a = z4, c7b = z4;

    float4 pa0, pa1, pb0, pb1;

    pa0 = aValid ? *(const float4*)(Aptr + 0) : z4;
    pa1 = aValid ? *(const float4*)(Aptr + 4) : z4;
    pb0 = *(const float4*)(Bptr + 0);
    pb1 = *(const float4*)(Bptr + 4);

    As[0][aCol + 0][aRow] = pa0.x;
    As[0][aCol + 1][aRow] = pa0.y;
    As[0][aCol + 2][aRow] = pa0.z;
    As[0][aCol + 3][aRow] = pa0.w;
    As[0][aCol + 4][aRow] = pa1.x;
    As[0][aCol + 5][aRow] = pa1.y;
    As[0][aCol + 6][aRow] = pa1.z;
    As[0][aCol + 7][aRow] = pa1.w;
    *(float4*)&Bs[0][bRow][bCol]     = pb0;
    *(float4*)&Bs[0][bRow][bCol + 4] = pb1;
    __syncthreads();

    const int NT = DH / 16;   // 32 tiles
    int buf = 0;

#define FMA_ROW(i, av)                                                        \
    c##i##a.x += (av) * b0.x; c##i##a.y += (av) * b0.y;                       \
    c##i##a.z += (av) * b0.z; c##i##a.w += (av) * b0.w;                       \
    c##i##b.x += (av) * b1.x; c##i##b.y += (av) * b1.y;                       \
    c##i##b.z += (av) * b1.z; c##i##b.w += (av) * b1.w;

#pragma unroll 1
    for (int kt = 0; kt < NT; kt++) {
        if (kt + 1 < NT) {
            const size_t off = (size_t)(kt + 1) * 16;
            pa0 = aValid ? *(const float4*)(Aptr + off) : z4;
            pa1 = aValid ? *(const float4*)(Aptr + off + 4) : z4;
            pb0 = *(const float4*)(Bptr + off * DH);
            pb1 = *(const float4*)(Bptr + off * DH + 4);
        }

#pragma unroll
        for (int kk = 0; kk < 16; kk++) {
            const float4 a0 = *(const float4*)&As[buf][kk][ty * 4];
            const float4 a1 = *(const float4*)&As[buf][kk][ty * 4 + 64];
            const float4 b0 = *(const float4*)&Bs[buf][kk][tx * 4];
            const float4 b1 = *(const float4*)&Bs[buf][kk][tx * 4 + 64];
            FMA_ROW(0, a0.x) FMA_ROW(1, a0.y) FMA_ROW(2, a0.z) FMA_ROW(3, a0.w)
            FMA_ROW(4, a1.x) FMA_ROW(5, a1.y) FMA_ROW(6, a1.z) FMA_ROW(7, a1.w)
        }

        if (kt + 1 < NT) {
            const int nb = buf ^ 1;
            As[nb][aCol + 0][aRow] = pa0.x;
            As[nb][aCol + 1][aRow] = pa0.y;
            As[nb][aCol + 2][aRow] = pa0.z;
            As[nb][aCol + 3][aRow] = pa0.w;
            As[nb][aCol + 4][aRow] = pa1.x;
            As[nb][aCol + 5][aRow] = pa1.y;
            As[nb][aCol + 6][aRow] = pa1.z;
            As[nb][aCol + 7][aRow] = pa1.w;
            *(float4*)&Bs[nb][bRow][bCol]     = pb0;
            *(float4*)&Bs[nb][bRow][bCol + 4] = pb1;
            __syncthreads();
            buf = nb;
        }
    }
#undef FMA_ROW

#define STORE_ROW(i, rowexpr)                                                 \
    {                                                                         \
        int row = (rowexpr);                                                  \
        if (row < M) {                                                        \
            float* cp = &C[(size_t)row * DH + bn * 128];                      \
            *(float4*)&cp[tx * 4]      = c##i##a;                             \
            *(float4*)&cp[tx * 4 + 64] = c##i##b;                             \
        }                                                                     \
    }
    STORE_ROW(0, bm * 128 + ty * 4 + 0)
    STORE_ROW(1, bm * 128 + ty * 4 + 1)
    STORE_ROW(2, bm * 128 + ty * 4 + 2)
    STORE_ROW(3, bm * 128 + ty * 4 + 3)
    STORE_ROW(4, bm * 128 + 64 + ty * 4 + 0)
    STORE_ROW(5, bm * 128 + 64 + ty * 4 + 1)
    STORE_ROW(6, bm * 128 + 64 + ty * 4 + 2)
    STORE_ROW(7, bm * 128 + 64 + ty * 4 + 3)
#undef STORE_ROW
}

// ---------------------------------------------------------------------------
// Aggregation body (shared by real kernel and the probe): identical code so
// the probe's ncu counters transfer exactly.
// ---------------------------------------------------------------------------
__device__ __forceinline__ void aggregate_body(const float* __restrict__ h,
                                               const float* __restrict__ bias,
                                               float* __restrict__ out,
                                               int do_relu) {
    int i = blockIdx.x;
    int t = threadIdx.x;           // 0..127, handles 4 floats
    int r0 = g_rowptr[i];
    int r1 = g_rowptr[i + 1];

    float4 a0 = make_float4(0.f, 0.f, 0.f, 0.f);
    float4 a1 = a0, a2 = a0, a3 = a0;

    int e = r0;
    for (; e + 3 < r1; e += 4) {
        int   s0 = g_csr_src[e],     s1 = g_csr_src[e + 1];
        int   s2 = g_csr_src[e + 2], s3 = g_csr_src[e + 3];
        float w0 = g_csr_norm[e],    w1 = g_csr_norm[e + 1];
        float w2 = g_csr_norm[e + 2], w3 = g_csr_norm[e + 3];
        float4 v0 = *(const float4*)&h[(size_t)s0 * DH + t * 4];
        float4 v1 = *(const float4*)&h[(size_t)s1 * DH + t * 4];
        float4 v2 = *(const float4*)&h[(size_t)s2 * DH + t * 4];
        float4 v3 = *(const float4*)&h[(size_t)s3 * DH + t * 4];
        a0.x += w0 * v0.x; a0.y += w0 * v0.y; a0.z += w0 * v0.z; a0.w += w0 * v0.w;
        a1.x += w1 * v1.x; a1.y += w1 * v1.y; a1.z += w1 * v1.z; a1.w += w1 * v1.w;
        a2.x += w2 * v2.x; a2.y += w2 * v2.y; a2.z += w2 * v2.z; a2.w += w2 * v2.w;
        a3.x += w3 * v3.x; a3.y += w3 * v3.y; a3.z += w3 * v3.z; a3.w += w3 * v3.w;
    }
    for (; e < r1; e++) {
        int   s = g_csr_src[e];
        float w = g_csr_norm[e];
        float4 v = *(const float4*)&h[(size_t)s * DH + t * 4];
        a0.x += w * v.x; a0.y += w * v.y; a0.z += w * v.z; a0.w += w * v.w;
    }

    float4 acc;
    acc.x = (a0.x + a1.x) + (a2.x + a3.x);
    acc.y = (a0.y + a1.y) + (a2.y + a3.y);
    acc.z = (a0.z + a1.z) + (a2.z + a3.z);
    acc.w = (a0.w + a1.w) + (a2.w + a3.w);

    float d = g_dinv[i];
    float w2 = d * d;
    float4 vs = *(const float4*)&h[(size_t)i * DH + t * 4];
    float4 b4 = *(const float4*)&bias[t * 4];
    acc.x += w2 * vs.x + b4.x;
    acc.y += w2 * vs.y + b4.y;
    acc.z += w2 * vs.z + b4.z;
    acc.w += w2 * vs.w + b4.w;
    if (do_relu) {
        acc.x = fmaxf(acc.x, 0.f); acc.y = fmaxf(acc.y, 0.f);
        acc.z = fmaxf(acc.z, 0.f); acc.w = fmaxf(acc.w, 0.f);
    }
    *(float4*)&out[(size_t)i * DH + t * 4] = acc;
}

__global__ __launch_bounds__(128) void aggregate_kernel(const float* __restrict__ h,
                                                        const float* __restrict__ bias,
                                                        float* __restrict__ out,
                                                        int do_relu) {
    aggregate_body(h, bias, out, do_relu);
}

// identical shape/code; dead output; exists only so ncu (4th launch) lands on
// an aggregate with real CSR + real h traffic
__global__ __launch_bounds__(128) void probe_aggregate_kernel(const float* __restrict__ h,
                                                              const float* __restrict__ bias) {
    aggregate_body(h, bias, g_probe, 1);
}

// ---------------------------------------------------------------------------
// Mean pool per graph (batch is sorted -> binary search the node range)
// ---------------------------------------------------------------------------
__global__ __launch_bounds__(128) void pool_kernel(const float* __restrict__ h,
                                                   const int* __restrict__ batch,
                                                   int enc) {
    int g = blockIdx.x;
    int t = threadIdx.x;

    int lo = 0, hi = NN;
    while (lo < hi) { int m = (lo + hi) >> 1; if (batch[m] < g) lo = m + 1; else hi = m; }
    int start = lo;
    lo = start; hi = NN;
    while (lo < hi) { int m = (lo + hi) >> 1; if (batch[m] < g + 1) lo = m + 1; else hi = m; }
    int end = lo;

    float4 a0 = make_float4(0.f, 0.f, 0.f, 0.f);
    float4 a1 = a0;
    int r = start;
    for (; r + 1 < end; r += 2) {
        float4 v0 = *(const float4*)&h[(size_t)r * DH + t * 4];
        float4 v1 = *(const float4*)&h[(size_t)(r + 1) * DH + t * 4];
        a0.x += v0.x; a0.y += v0.y; a0.z += v0.z; a0.w += v0.w;
        a1.x += v1.x; a1.y += v1.y; a1.z += v1.z; a1.w += v1.w;
    }
    if (r < end) {
        float4 v = *(const float4*)&h[(size_t)r * DH + t * 4];
        a0.x += v.x; a0.y += v.y; a0.z += v.z; a0.w += v.w;
    }
    float inv = 1.0f / fmaxf((float)(end - start), 1.0f);
    float4 acc;
    acc.x = (a0.x + a1.x) * inv;
    acc.y = (a0.y + a1.y) * inv;
    acc.z = (a0.z + a1.z) * inv;
    acc.w = (a0.w + a1.w) * inv;
    *(float4*)&g_pooled[enc][g * DH + t * 4] = acc;
}

// ---------------------------------------------------------------------------
// Final pairwise distance: out[g] = || pooled_a[g] - pooled_b[g] + 1e-6 ||_2
// ---------------------------------------------------------------------------
__global__ __launch_bounds__(128) void dist_kernel(float* __restrict__ out) {
    int g = blockIdx.x;
    int t = threadIdx.x;
    const float* pa = &g_pooled[0][g * DH];
    const float* pb = &g_pooled[1][g * DH];
    float4 a = *(const float4*)&pa[t * 4];
    float4 b = *(const float4*)&pb[t * 4];
    float dx = a.x - b.x + 1e-6f;
    float dy = a.y - b.y + 1e-6f;
    float dz = a.z - b.z + 1e-6f;
    float dw = a.w - b.w + 1e-6f;
    float s = dx * dx + dy * dy + dz * dz + dw * dw;

    __shared__ float red[128];
    red[t] = s;
    __syncthreads();
    for (int off = 64; off > 0; off >>= 1) {
        if (t < off) red[t] += red[t + off];
        __syncthreads();
    }
    if (t == 0) out[g] = sqrtf(red[0]);
}

// ---------------------------------------------------------------------------
// launch
// ---------------------------------------------------------------------------
extern "C" void kernel_launch(void* const* d_in, const int* in_sizes, int n_in,
                              void* d_out, int out_size) {
    const float* x_a     = (const float*)d_in[0];
    const int*   ei_a    = (const int*)  d_in[1];
    const int*   batch_a = (const int*)  d_in[2];
    const float* x_b     = (const float*)d_in[3];
    const int*   ei_b    = (const int*)  d_in[4];
    const int*   batch_b = (const int*)  d_in[5];
    const float* W1 = (const float*)d_in[6];
    const float* b1 = (const float*)d_in[7];
    const float* W2 = (const float*)d_in[8];
    const float* b2 = (const float*)d_in[9];
    const float* W3 = (const float*)d_in[10];
    const float* b3 = (const float*)d_in[11];
    float* out = (float*)d_out;

    const dim3 gemm_grid(DH / 128, (NN + 127) / 128);   // (4, 157)
    const int  eblocks = (EE + 255) / 256;

    for (int enc = 0; enc < 2; enc++) {
        const float* x   = enc ? x_b : x_a;
        const int*   ei  = enc ? ei_b : ei_a;
        const int*   bat = enc ? batch_b : batch_a;
        const int* src = ei;
        const int* dst = ei + EE;

        // CSR build (g_deg is zero on entry; scan restores that invariant)
        count_deg_kernel<<<eblocks, 256>>>(dst);        // launch 1
        scan_kernel<<<1, 1024>>>();                     // launch 2
        fill_csr_kernel<<<eblocks, 256>>>(src, dst);    // launch 3

        // PROBE (enc A only): identical aggregate over real CSR, h = x,
        // dead output. 4th launch -> this is what ncu profiles.
        if (enc == 0)
            probe_aggregate_kernel<<<NN, 128>>>(x, b1); // launch 4

        // layer 1
        sgemm_kernel<<<gemm_grid, 256>>>(x, W1, g_gemm, NN);
        aggregate_kernel<<<NN, 128>>>(g_gemm, b1, g_x, 1);
        // layer 2
        sgemm_kernel<<<gemm_grid, 256>>>(g_x, W2, g_gemm, NN);
        aggregate_kernel<<<NN, 128>>>(g_gemm, b2, g_x, 1);
        // layer 3
        sgemm_kernel<<<gemm_grid, 256>>>(g_x, W3, g_gemm, NN);
        aggregate_kernel<<<NN, 128>>>(g_gemm, b3, g_x, 0);

        // mean pool
        pool_kernel<<<GG, 128>>>(g_x, bat, enc);
    }

    dist_kernel<<<GG, 128>>>(out);
}

// round 5
// speedup vs baseline: 17.2938x; 17.2725x over previous
#include <cuda_runtime.h>

// ---------------------------------------------------------------------------
// SiameseBrainNet: 2x (3-layer GCN + mean pool) + pairwise distance
// N=20000 nodes, E=640000 edges, D=H=512, G=64 graphs
// R5: SINGLE persistent mega-kernel. All phases separated by a hand-rolled
//     grid barrier (monotonic generation counter; replay-safe). 264 blocks x
//     256 threads, launch_bounds(256,2) guarantees co-residency (<=128 regs,
//     2 CTA/SM -> capacity 296 >= 264 on 148-SM B300 / 152-SM GB300).
// ---------------------------------------------------------------------------

#define NN 20000
#define EE 640000
#define DH 512
#define GG 64
#define NB 264
#define TPB 256
#define MTILES 157            // ceil(20000/128)
#define NTILE (4 * MTILES)    // 4 column tiles of 128

// ---- scratch (device globals; no allocation allowed) ----------------------
__device__ float g_gemm[NN * DH];
__device__ float g_x[NN * DH];
__device__ int   g_deg[NN];        // INVARIANT: all zero at kernel entry
__device__ int   g_rowptr[NN + 1];
__device__ int   g_cursor[NN];
__device__ float g_dinv[NN];
__device__ int   g_csr_src[EE];
__device__ float g_csr_norm[EE];
__device__ float g_pooled[2][GG * DH];
__device__ unsigned g_count;       // barrier arrival count (self-resetting)
__device__ unsigned g_gen;         // barrier generation (monotonic)

// ---------------------------------------------------------------------------
// Grid-wide barrier. All NB blocks must be resident (guaranteed by
// launch_bounds + grid size). 'target' = generation to wait for.
// ---------------------------------------------------------------------------
__device__ __forceinline__ void gsync(unsigned target) {
    __syncthreads();
    if (threadIdx.x == 0) {
        __threadfence();
        if (atomicAdd(&g_count, 1u) == NB - 1u) {
            atomicExch(&g_count, 0u);
            __threadfence();
            atomicAdd(&g_gen, 1u);
        } else {
            while (*((volatile unsigned*)&g_gen) < target) __nanosleep(64);
        }
        __threadfence();
    }
    __syncthreads();
}

// ---------------------------------------------------------------------------
// GEMM phase: C[M,512] = A[M,512] @ B[512,512], tiles block-strided.
// 128x128 tile, BK=16, double-buffered smem, 8x8/thread, named registers.
// ---------------------------------------------------------------------------
__device__ void gemm_phase(const float* __restrict__ A, const float* __restrict__ B,
                           float* __restrict__ C, float* sA, float* sB) {
    const int tid = threadIdx.x;
    const int aRow = tid >> 1;
    const int aCol = (tid & 1) * 8;
    const int bRow = tid >> 4;
    const int bCol = (tid & 15) * 8;
    const int tx = tid & 15, ty = tid >> 4;
    const float4 z4 = make_float4(0.f, 0.f, 0.f, 0.f);

#define AS(b, k, m) sA[(((b) * 16 + (k)) << 7) + (m)]
#define BS(b, k, n) sB[(((b) * 16 + (k)) << 7) + (n)]

    for (int t = blockIdx.x; t < NTILE; t += NB) {
        const int bm = t >> 2, bn = t & 3;

        const int aRowG = bm * 128 + aRow;
        const bool aValid = (aRowG < NN);
        const float* Aptr = A + (size_t)aRowG * DH + aCol;
        const float* Bptr = B + (size_t)bRow * DH + bn * 128 + bCol;

        float4 c0a = z4, c0b = z4, c1a = z4, c1b = z4;
        float4 c2a = z4, c2b = z4, c3a = z4, c3b = z4;
        float4 c4a = z4, c4b = z4, c5a = z4, c5b = z4;
        float4 c6a = z4, c6b = z4, c7a = z4, c7b = z4;

        float4 pa0, pa1, pb0, pb1;

        pa0 = aValid ? *(const float4*)(Aptr + 0) : z4;
        pa1 = aValid ? *(const float4*)(Aptr + 4) : z4;
        pb0 = *(const float4*)(Bptr + 0);
        pb1 = *(const float4*)(Bptr + 4);

        AS(0, aCol + 0, aRow) = pa0.x;
        AS(0, aCol + 1, aRow) = pa0.y;
        AS(0, aCol + 2, aRow) = pa0.z;
        AS(0, aCol + 3, aRow) = pa0.w;
        AS(0, aCol + 4, aRow) = pa1.x;
        AS(0, aCol + 5, aRow) = pa1.y;
        AS(0, aCol + 6, aRow) = pa1.z;
        AS(0, aCol + 7, aRow) = pa1.w;
        *(float4*)&BS(0, bRow, bCol)     = pb0;
        *(float4*)&BS(0, bRow, bCol + 4) = pb1;
        __syncthreads();

        const int NT = DH / 16;   // 32
        int buf = 0;

#define FMA_ROW(i, av)                                                        \
        c##i##a.x += (av) * b0.x; c##i##a.y += (av) * b0.y;                   \
        c##i##a.z += (av) * b0.z; c##i##a.w += (av) * b0.w;                   \
        c##i##b.x += (av) * b1.x; c##i##b.y += (av) * b1.y;                   \
        c##i##b.z += (av) * b1.z; c##i##b.w += (av) * b1.w;

#pragma unroll 1
        for (int kt = 0; kt < NT; kt++) {
            if (kt + 1 < NT) {
                const size_t off = (size_t)(kt + 1) * 16;
                pa0 = aValid ? *(const float4*)(Aptr + off) : z4;
                pa1 = aValid ? *(const float4*)(Aptr + off + 4) : z4;
                pb0 = *(const float4*)(Bptr + off * DH);
                pb1 = *(const float4*)(Bptr + off * DH + 4);
            }

#pragma unroll
            for (int kk = 0; kk < 16; kk++) {
                const float4 a0 = *(const float4*)&AS(buf, kk, ty * 4);
                const float4 a1 = *(const float4*)&AS(buf, kk, ty * 4 + 64);
                const float4 b0 = *(const float4*)&BS(buf, kk, tx * 4);
                const float4 b1 = *(const float4*)&BS(buf, kk, tx * 4 + 64);
                FMA_ROW(0, a0.x) FMA_ROW(1, a0.y) FMA_ROW(2, a0.z) FMA_ROW(3, a0.w)
                FMA_ROW(4, a1.x) FMA_ROW(5, a1.y) FMA_ROW(6, a1.z) FMA_ROW(7, a1.w)
            }

            if (kt + 1 < NT) {
                const int nb = buf ^ 1;
                AS(nb, aCol + 0, aRow) = pa0.x;
                AS(nb, aCol + 1, aRow) = pa0.y;
                AS(nb, aCol + 2, aRow) = pa0.z;
                AS(nb, aCol + 3, aRow) = pa0.w;
                AS(nb, aCol + 4, aRow) = pa1.x;
                AS(nb, aCol + 5, aRow) = pa1.y;
                AS(nb, aCol + 6, aRow) = pa1.z;
                AS(nb, aCol + 7, aRow) = pa1.w;
                *(float4*)&BS(nb, bRow, bCol)     = pb0;
                *(float4*)&BS(nb, bRow, bCol + 4) = pb1;
                __syncthreads();
                buf = nb;
            }
        }
#undef FMA_ROW

#define STORE_ROW(i, rowexpr)                                                 \
        {                                                                     \
            int row = (rowexpr);                                              \
            if (row < NN) {                                                   \
                float* cp = &C[(size_t)row * DH + bn * 128];                  \
                *(float4*)&cp[tx * 4]      = c##i##a;                         \
                *(float4*)&cp[tx * 4 + 64] = c##i##b;                         \
            }                                                                 \
        }
        STORE_ROW(0, bm * 128 + ty * 4 + 0)
        STORE_ROW(1, bm * 128 + ty * 4 + 1)
        STORE_ROW(2, bm * 128 + ty * 4 + 2)
        STORE_ROW(3, bm * 128 + ty * 4 + 3)
        STORE_ROW(4, bm * 128 + 64 + ty * 4 + 0)
        STORE_ROW(5, bm * 128 + 64 + ty * 4 + 1)
        STORE_ROW(6, bm * 128 + 64 + ty * 4 + 2)
        STORE_ROW(7, bm * 128 + 64 + ty * 4 + 3)
#undef STORE_ROW
    }
#undef AS
#undef BS
}

// ---------------------------------------------------------------------------
// Aggregate phase: 2 nodes per block (128 lanes each), block-strided.
// out[i] = sum_{e: dst==i} norm_e * h[src_e] + h[i]*dinv[i]^2 + b
// ---------------------------------------------------------------------------
__device__ void agg_phase(const float* __restrict__ h, const float* __restrict__ bias,
                          float* __restrict__ outp, int do_relu) {
    const int sub = threadIdx.x >> 7;   // 0 or 1
    const int t   = threadIdx.x & 127;  // float4 lane
    const float4 b4 = *(const float4*)&bias[t * 4];

    for (int i = blockIdx.x * 2 + sub; i < NN; i += NB * 2) {
        int r0 = g_rowptr[i];
        int r1 = g_rowptr[i + 1];

        float4 a0 = make_float4(0.f, 0.f, 0.f, 0.f);
        float4 a1 = a0, a2 = a0, a3 = a0;

        int e = r0;
        for (; e + 3 < r1; e += 4) {
            int   s0 = g_csr_src[e],     s1 = g_csr_src[e + 1];
            int   s2 = g_csr_src[e + 2], s3 = g_csr_src[e + 3];
            float w0 = g_csr_norm[e],    w1 = g_csr_norm[e + 1];
            float w2 = g_csr_norm[e + 2], w3 = g_csr_norm[e + 3];
            float4 v0 = *(const float4*)&h[(size_t)s0 * DH + t * 4];
            float4 v1 = *(const float4*)&h[(size_t)s1 * DH + t * 4];
            float4 v2 = *(const float4*)&h[(size_t)s2 * DH + t * 4];
            float4 v3 = *(const float4*)&h[(size_t)s3 * DH + t * 4];
            a0.x += w0 * v0.x; a0.y += w0 * v0.y; a0.z += w0 * v0.z; a0.w += w0 * v0.w;
            a1.x += w1 * v1.x; a1.y += w1 * v1.y; a1.z += w1 * v1.z; a1.w += w1 * v1.w;
            a2.x += w2 * v2.x; a2.y += w2 * v2.y; a2.z += w2 * v2.z; a2.w += w2 * v2.w;
            a3.x += w3 * v3.x; a3.y += w3 * v3.y; a3.z += w3 * v3.z; a3.w += w3 * v3.w;
        }
        for (; e < r1; e++) {
            int   s = g_csr_src[e];
            float w = g_csr_norm[e];
            float4 v = *(const float4*)&h[(size_t)s * DH + t * 4];
            a0.x += w * v.x; a0.y += w * v.y; a0.z += w * v.z; a0.w += w * v.w;
        }

        float4 acc;
        acc.x = (a0.x + a1.x) + (a2.x + a3.x);
        acc.y = (a0.y + a1.y) + (a2.y + a3.y);
        acc.z = (a0.z + a1.z) + (a2.z + a3.z);
        acc.w = (a0.w + a1.w) + (a2.w + a3.w);

        float d = g_dinv[i];
        float wd = d * d;
        float4 vs = *(const float4*)&h[(size_t)i * DH + t * 4];
        acc.x += wd * vs.x + b4.x;
        acc.y += wd * vs.y + b4.y;
        acc.z += wd * vs.z + b4.z;
        acc.w += wd * vs.w + b4.w;
        if (do_relu) {
            acc.x = fmaxf(acc.x, 0.f); acc.y = fmaxf(acc.y, 0.f);
            acc.z = fmaxf(acc.z, 0.f); acc.w = fmaxf(acc.w, 0.f);
        }
        *(float4*)&outp[(size_t)i * DH + t * 4] = acc;
    }
}

// ---------------------------------------------------------------------------
// Pool phase: blocks 0..63 each handle one graph (256 threads, float2 lanes)
// ---------------------------------------------------------------------------
__device__ void pool_phase(const float* __restrict__ h, const int* __restrict__ batch,
                           int enc) {
    int g = blockIdx.x;
    if (g >= GG) return;                // no syncthreads below
    int t = threadIdx.x;                // 0..255, float2 lane

    int lo = 0, hi = NN;
    while (lo < hi) { int m = (lo + hi) >> 1; if (batch[m] < g) lo = m + 1; else hi = m; }
    int start = lo;
    lo = start; hi = NN;
    while (lo < hi) { int m = (lo + hi) >> 1; if (batch[m] < g + 1) lo = m + 1; else hi = m; }
    int end = lo;

    float2 a0 = make_float2(0.f, 0.f), a1 = a0;
    int r = start;
    for (; r + 1 < end; r += 2) {
        float2 v0 = *(const float2*)&h[(size_t)r * DH + t * 2];
        float2 v1 = *(const float2*)&h[(size_t)(r + 1) * DH + t * 2];
        a0.x += v0.x; a0.y += v0.y;
        a1.x += v1.x; a1.y += v1.y;
    }
    if (r < end) {
        float2 v = *(const float2*)&h[(size_t)r * DH + t * 2];
        a0.x += v.x; a0.y += v.y;
    }
    float inv = 1.0f / fmaxf((float)(end - start), 1.0f);
    float2 acc = make_float2((a0.x + a1.x) * inv, (a0.y + a1.y) * inv);
    *(float2*)&g_pooled[enc][g * DH + t * 2] = acc;
}

// ---------------------------------------------------------------------------
// Dist phase: blocks 0..63, one graph each; 256 threads reduce 512 dims
// ---------------------------------------------------------------------------
__device__ void dist_phase(float* __restrict__ out, float* sred) {
    int g = blockIdx.x;
    if (g >= GG) return;                // whole block skips (uniform)
    int t = threadIdx.x;

    float2 a = *(const float2*)&g_pooled[0][g * DH + t * 2];
    float2 b = *(const float2*)&g_pooled[1][g * DH + t * 2];
    float dx = a.x - b.x + 1e-6f;
    float dy = a.y - b.y + 1e-6f;
    float s = dx * dx + dy * dy;

    sred[t] = s;
    __syncthreads();
    for (int off = 128; off > 0; off >>= 1) {
        if (t < off) sred[t] += sred[t + off];
        __syncthreads();
    }
    if (t == 0) out[g] = sqrtf(sred[0]);
}

// ---------------------------------------------------------------------------
// The mega kernel
// ---------------------------------------------------------------------------
__global__ __launch_bounds__(TPB, 2) void mega_kernel(
    const float* __restrict__ x_a, const int* __restrict__ ei_a,
    const int* __restrict__ batch_a,
    const float* __restrict__ x_b, const int* __restrict__ ei_b,
    const int* __restrict__ batch_b,
    const float* __restrict__ W1, const float* __restrict__ b1,
    const float* __restrict__ W2, const float* __restrict__ b2,
    const float* __restrict__ W3, const float* __restrict__ b3,
    float* __restrict__ out)
{
    __shared__ float sA[2 * 16 * 128];
    __shared__ float sB[2 * 16 * 128];

    const int tid = threadIdx.x, bid = blockIdx.x;
    unsigned target = *((volatile unsigned*)&g_gen);   // stable at entry

    for (int enc = 0; enc < 2; enc++) {
        const float* x    = enc ? x_b : x_a;
        const int* srcv   = enc ? ei_b : ei_a;
        const int* dstv   = srcv + EE;
        const int* batch  = enc ? batch_b : batch_a;

        // ---- count degrees (g_deg zero on entry) ----
        for (int e = bid * TPB + tid; e < EE; e += NB * TPB)
            atomicAdd(&g_deg[dstv[e]], 1);
        gsync(++target);

        // ---- scan + dinv + cursor + re-zero deg (block 0) ----
        if (bid == 0) {
            int* sh = (int*)sA;
            const int chunk = (NN + TPB - 1) / TPB;   // 79
            int base = tid * chunk;
            int local = 0;
            for (int j = 0; j < chunk; j++) {
                int idx = base + j;
                if (idx < NN) local += g_deg[idx];
            }
            sh[tid] = local;
            __syncthreads();
            for (int off = 1; off < TPB; off <<= 1) {
                int v = (tid >= off) ? sh[tid - off] : 0;
                __syncthreads();
                sh[tid] += v;
                __syncthreads();
            }
            int run = tid ? sh[tid - 1] : 0;
            for (int j = 0; j < chunk; j++) {
                int idx = base + j;
                if (idx < NN) {
                    int d = g_deg[idx];
                    g_deg[idx]    = 0;                // restore invariant
                    g_rowptr[idx] = run;
                    g_cursor[idx] = run;
                    g_dinv[idx]   = rsqrtf((float)d + 1.0f);
                    run += d;
                }
            }
            if (tid == TPB - 1) g_rowptr[NN] = sh[TPB - 1];
        }
        gsync(++target);

        // ---- fill CSR ----
        for (int e = bid * TPB + tid; e < EE; e += NB * TPB) {
            int s = srcv[e], d = dstv[e];
            int pos = atomicAdd(&g_cursor[d], 1);
            g_csr_src[pos]  = s;
            g_csr_norm[pos] = g_dinv[s] * g_dinv[d];
        }
        gsync(++target);

        // ---- 3 GCN layers ----
        const float* hin = x;
        for (int l = 0; l < 3; l++) {
            const float* W  = (l == 0) ? W1 : (l == 1) ? W2 : W3;
            const float* bb = (l == 0) ? b1 : (l == 1) ? b2 : b3;
            gemm_phase(hin, W, g_gemm, sA, sB);
            gsync(++target);
            agg_phase(g_gemm, bb, g_x, l < 2);
            gsync(++target);
            hin = g_x;
        }

        // ---- mean pool ----
        pool_phase(g_x, batch, enc);
        gsync(++target);
    }

    // ---- pairwise distance ----
    dist_phase(out, sA);
}

// ---------------------------------------------------------------------------
// launch: ONE kernel
// ---------------------------------------------------------------------------
extern "C" void kernel_launch(void* const* d_in, const int* in_sizes, int n_in,
                              void* d_out, int out_size) {
    const float* x_a     = (const float*)d_in[0];
    const int*   ei_a    = (const int*)  d_in[1];
    const int*   batch_a = (const int*)  d_in[2];
    const float* x_b     = (const float*)d_in[3];
    const int*   ei_b    = (const int*)  d_in[4];
    const int*   batch_b = (const int*)  d_in[5];
    const float* W1 = (const float*)d_in[6];
    const float* b1 = (const float*)d_in[7];
    const float* W2 = (const float*)d_in[8];
    const float* b2 = (const float*)d_in[9];
    const float* W3 = (const float*)d_in[10];
    const float* b3 = (const float*)d_in[11];
    float* out = (float*)d_out;

    mega_kernel<<<NB, TPB>>>(x_a, ei_a, batch_a, x_b, ei_b, batch_b,
                             W1, b1, W2, b2, W3, b3, out);
}

// round 7
// speedup vs baseline: 19.3809x; 1.1207x over previous
#include <cuda_runtime.h>
#include <cuda_bf16.h>
#include <cstdint>

// ---------------------------------------------------------------------------
// SiameseBrainNet: persistent mega-kernel + mma.sync split-bf16 GEMM
// N=20000, E=640000, D=H=512, G=64
// ---------------------------------------------------------------------------

#define NN 20000
#define EE 640000
#define DH 512
#define GG 64
#define NB 148            // 1 CTA/SM
#define TPB 256
#define MT 157            // ceil(NN/128)
#define NTILE (4 * MT)    // 628 output tiles (128x128)

#define KSTR 80           // smem row stride in bf16 (64 data + 16 pad)
#define TILE_BYTES (128 * KSTR * 2)   // 20480
#define SM_AHI 0
#define SM_ALO (1 * TILE_BYTES)
#define SM_BHI (2 * TILE_BYTES)
#define SM_BLO (3 * TILE_BYTES)
#define SM_RED (4 * TILE_BYTES)       // 81920
#define SMEM_BYTES (SM_RED + 1024)    // 82944

// ---- scratch ---------------------------------------------------------------
__device__ float g_gemm[NN * DH];
__device__ float g_x[NN * DH];
__device__ __nv_bfloat16 g_ahi[NN * DH];
__device__ __nv_bfloat16 g_alo[NN * DH];
__device__ __nv_bfloat16 g_wthi[3 * DH * DH];   // W^T split, [l][n][k]
__device__ __nv_bfloat16 g_wtlo[3 * DH * DH];
__device__ int   g_deg[NN];        // INVARIANT: zero at kernel entry
__device__ int   g_rowptr[NN + 1];
__device__ int   g_cursor[NN];
__device__ float g_dinv[NN];
__device__ int   g_csr_src[EE];
__device__ float g_csr_norm[EE];
__device__ float g_pooled[2][GG * DH];
__device__ unsigned g_count, g_gen;

// ---- grid barrier -----------------------------------------------------------
__device__ __forceinline__ void gsync(unsigned target) {
    __syncthreads();
    if (threadIdx.x == 0) {
        __threadfence();
        if (atomicAdd(&g_count, 1u) == NB - 1u) {
            atomicExch(&g_count, 0u);
            __threadfence();
            atomicAdd(&g_gen, 1u);
        } else {
            while (*((volatile unsigned*)&g_gen) < target) __nanosleep(64);
        }
        __threadfence();
    }
    __syncthreads();
}

// ---- mma.sync m16n8k16 bf16 (f32 accum) --------------------------------------
__device__ __forceinline__ void mma16816(float* d,
                                         uint32_t a0, uint32_t a1, uint32_t a2, uint32_t a3,
                                         uint32_t b0, uint32_t b1) {
    asm volatile(
        "mma.sync.aligned.m16n8k16.row.col.f32.bf16.bf16.f32 "
        "{%0,%1,%2,%3}, {%4,%5,%6,%7}, {%8,%9}, {%0,%1,%2,%3};"
        : "+f"(d[0]), "+f"(d[1]), "+f"(d[2]), "+f"(d[3])
        : "r"(a0), "r"(a1), "r"(a2), "r"(a3), "r"(b0), "r"(b1));
}

// gmem bf16 [.,512] -> smem tile 128x64 (stride KSTR), rows>=nrows zero-filled
__device__ __forceinline__ void fill_tile(__nv_bfloat16* smt,
                                          const __nv_bfloat16* __restrict__ g,
                                          int row0, int kc, int nrows) {
    const int tid = threadIdx.x;
#pragma unroll
    for (int i = 0; i < 4; i++) {
        int idx = i * 256 + tid;       // 0..1023
        int r   = idx >> 3;            // 0..127
        int c8  = (idx & 7) * 8;       // 0..56
        uint4 v = make_uint4(0u, 0u, 0u, 0u);
        int gr = row0 + r;
        if (gr < nrows)
            v = *(const uint4*)(g + (size_t)gr * DH + kc + c8);
        *(uint4*)(smt + r * KSTR + c8) = v;
    }
}

// ---- GEMM phase: C[NN,512] = A @ W, split-bf16 x3, fp32 accum ----------------
__device__ void gemm_phase(unsigned char* sm,
                           const __nv_bfloat16* __restrict__ Whi,
                           const __nv_bfloat16* __restrict__ Wlo,
                           float* __restrict__ C) {
    __nv_bfloat16* Ahi_s = (__nv_bfloat16*)(sm + SM_AHI);
    __nv_bfloat16* Alo_s = (__nv_bfloat16*)(sm + SM_ALO);
    __nv_bfloat16* Bhi_s = (__nv_bfloat16*)(sm + SM_BHI);
    __nv_bfloat16* Blo_s = (__nv_bfloat16*)(sm + SM_BLO);

    const int tid  = threadIdx.x;
    const int lane = tid & 31, warp = tid >> 5;
    const int wm = warp & 3;        // 0..3 : 32-row group
    const int wn = warp >> 2;       // 0..1 : 64-col group
    const int g  = lane >> 2;       // 0..7
    const int tg = lane & 3;        // 0..3

    for (int t = blockIdx.x; t < NTILE; t += NB) {
        const int bm = t >> 2, bn = t & 3;

        float acc[2][8][4];
#pragma unroll
        for (int mt = 0; mt < 2; mt++)
#pragma unroll
            for (int nt = 0; nt < 8; nt++)
#pragma unroll
                for (int q = 0; q < 4; q++) acc[mt][nt][q] = 0.0f;

#pragma unroll 1
        for (int kc8 = 0; kc8 < 8; kc8++) {
            __syncthreads();   // previous k-chunk fully consumed
            fill_tile(Ahi_s, g_ahi, bm * 128, kc8 * 64, NN);
            fill_tile(Alo_s, g_alo, bm * 128, kc8 * 64, NN);
            fill_tile(Bhi_s, Whi,   bn * 128, kc8 * 64, 1 << 30);
            fill_tile(Blo_s, Wlo,   bn * 128, kc8 * 64, 1 << 30);
            __syncthreads();

#pragma unroll
            for (int ks = 0; ks < 64; ks += 16) {
                // B fragments (shared across both m-tiles)
                uint32_t bh[8][2], bl[8][2];
#pragma unroll
                for (int nt = 0; nt < 8; nt++) {
                    int n = wn * 64 + nt * 8 + g;
                    const __nv_bfloat16* bp  = Bhi_s + n * KSTR + ks + 2 * tg;
                    const __nv_bfloat16* blp = Blo_s + n * KSTR + ks + 2 * tg;
                    bh[nt][0] = *(const uint32_t*)bp;
                    bh[nt][1] = *(const uint32_t*)(bp + 8);
                    bl[nt][0] = *(const uint32_t*)blp;
                    bl[nt][1] = *(const uint32_t*)(blp + 8);
                }
#pragma unroll
                for (int mt = 0; mt < 2; mt++) {
                    int r = wm * 32 + mt * 16;
                    const __nv_bfloat16* ap  = Ahi_s + (r + g) * KSTR + ks + 2 * tg;
                    const __nv_bfloat16* alp = Alo_s + (r + g) * KSTR + ks + 2 * tg;
                    uint32_t ah0 = *(const uint32_t*)ap;
                    uint32_t ah1 = *(const uint32_t*)(ap + 8 * KSTR);
                    uint32_t ah2 = *(const uint32_t*)(ap + 8);
                    uint32_t ah3 = *(const uint32_t*)(ap + 8 * KSTR + 8);
                    uint32_t al0 = *(const uint32_t*)alp;
                    uint32_t al1 = *(const uint32_t*)(alp + 8 * KSTR);
                    uint32_t al2 = *(const uint32_t*)(alp + 8);
                    uint32_t al3 = *(const uint32_t*)(alp + 8 * KSTR + 8);
#pragma unroll
                    for (int nt = 0; nt < 8; nt++) {
                        mma16816(acc[mt][nt], ah0, ah1, ah2, ah3, bh[nt][0], bh[nt][1]);
                        mma16816(acc[mt][nt], al0, al1, al2, al3, bh[nt][0], bh[nt][1]);
                        mma16816(acc[mt][nt], ah0, ah1, ah2, ah3, bl[nt][0], bl[nt][1]);
                    }
                }
            }
        }

        // epilogue: D(16x8) frag -> c0,c1 at (g, 2tg), c2,c3 at (g+8, 2tg)
#pragma unroll
        for (int mt = 0; mt < 2; mt++) {
            int row0 = bm * 128 + wm * 32 + mt * 16 + g;
#pragma unroll
            for (int nt = 0; nt < 8; nt++) {
                int col = bn * 128 + wn * 64 + nt * 8 + 2 * tg;
                if (row0 < NN)
                    *(float2*)&C[(size_t)row0 * DH + col] =
                        make_float2(acc[mt][nt][0], acc[mt][nt][1]);
                if (row0 + 8 < NN)
                    *(float2*)&C[(size_t)(row0 + 8) * DH + col] =
                        make_float2(acc[mt][nt][2], acc[mt][nt][3]);
            }
        }
        __syncthreads();
    }
}

// ---- aggregation (fused bf16 split for layers 0,1) --------------------------
__device__ __forceinline__ void bf_split(float v, __nv_bfloat16& h, __nv_bfloat16& l) {
    h = __float2bfloat16(v);
    l = __float2bfloat16(v - __bfloat162float(h));
}

__device__ void agg_phase(const float* __restrict__ h, const float* __restrict__ bias, int l) {
    const int sub = threadIdx.x >> 7;
    const int t   = threadIdx.x & 127;
    const float4 b4 = *(const float4*)&bias[t * 4];

    for (int i = blockIdx.x * 2 + sub; i < NN; i += NB * 2) {
        int r0 = g_rowptr[i];
        int r1 = g_rowptr[i + 1];

        float4 a0 = make_float4(0.f, 0.f, 0.f, 0.f);
        float4 a1 = a0, a2 = a0, a3 = a0;

        int e = r0;
        for (; e + 3 < r1; e += 4) {
            int   s0 = g_csr_src[e],     s1 = g_csr_src[e + 1];
            int   s2 = g_csr_src[e + 2], s3 = g_csr_src[e + 3];
            float w0 = g_csr_norm[e],    w1 = g_csr_norm[e + 1];
            float w2 = g_csr_norm[e + 2], w3 = g_csr_norm[e + 3];
            float4 v0 = *(const float4*)&h[(size_t)s0 * DH + t * 4];
            float4 v1 = *(const float4*)&h[(size_t)s1 * DH + t * 4];
            float4 v2 = *(const float4*)&h[(size_t)s2 * DH + t * 4];
            float4 v3 = *(const float4*)&h[(size_t)s3 * DH + t * 4];
            a0.x += w0 * v0.x; a0.y += w0 * v0.y; a0.z += w0 * v0.z; a0.w += w0 * v0.w;
            a1.x += w1 * v1.x; a1.y += w1 * v1.y; a1.z += w1 * v1.z; a1.w += w1 * v1.w;
            a2.x += w2 * v2.x; a2.y += w2 * v2.y; a2.z += w2 * v2.z; a2.w += w2 * v2.w;
            a3.x += w3 * v3.x; a3.y += w3 * v3.y; a3.z += w3 * v3.z; a3.w += w3 * v3.w;
        }
        for (; e < r1; e++) {
            int   s = g_csr_src[e];
            float w = g_csr_norm[e];
            float4 v = *(const float4*)&h[(size_t)s * DH + t * 4];
            a0.x += w * v.x; a0.y += w * v.y; a0.z += w * v.z; a0.w += w * v.w;
        }

        float4 acc;
        acc.x = (a0.x + a1.x) + (a2.x + a3.x);
        acc.y = (a0.y + a1.y) + (a2.y + a3.y);
        acc.z = (a0.z + a1.z) + (a2.z + a3.z);
        acc.w = (a0.w + a1.w) + (a2.w + a3.w);

        float d = g_dinv[i];
        float wd = d * d;
        float4 vs = *(const float4*)&h[(size_t)i * DH + t * 4];
        acc.x += wd * vs.x + b4.x;
        acc.y += wd * vs.y + b4.y;
        acc.z += wd * vs.z + b4.z;
        acc.w += wd * vs.w + b4.w;

        if (l < 2) {   // relu + split into bf16 hi/lo for next GEMM
            acc.x = fmaxf(acc.x, 0.f); acc.y = fmaxf(acc.y, 0.f);
            acc.z = fmaxf(acc.z, 0.f); acc.w = fmaxf(acc.w, 0.f);
            __nv_bfloat162 h01, h23, l01, l23;
            bf_split(acc.x, h01.x, l01.x); bf_split(acc.y, h01.y, l01.y);
            bf_split(acc.z, h23.x, l23.x); bf_split(acc.w, h23.y, l23.y);
            __nv_bfloat162* hp = (__nv_bfloat162*)(g_ahi + (size_t)i * DH + t * 4);
            __nv_bfloat162* lp = (__nv_bfloat162*)(g_alo + (size_t)i * DH + t * 4);
            hp[0] = h01; hp[1] = h23;
            lp[0] = l01; lp[1] = l23;
        } else {       // last layer: fp32 for pooling
            *(float4*)&g_x[(size_t)i * DH + t * 4] = acc;
        }
    }
}

// ---- pool / dist -------------------------------------------------------------
__device__ void pool_phase(const float* __restrict__ h, const int* __restrict__ batch, int enc) {
    int g = blockIdx.x;
    if (g >= GG) return;
    int t = threadIdx.x;   // float2 lane

    int lo = 0, hi = NN;
    while (lo < hi) { int m = (lo + hi) >> 1; if (batch[m] < g) lo = m + 1; else hi = m; }
    int start = lo;
    lo = start; hi = NN;
    while (lo < hi) { int m = (lo + hi) >> 1; if (batch[m] < g + 1) lo = m + 1; else hi = m; }
    int end = lo;

    float2 a0 = make_float2(0.f, 0.f), a1 = a0;
    int r = start;
    for (; r + 1 < end; r += 2) {
        float2 v0 = *(const float2*)&h[(size_t)r * DH + t * 2];
        float2 v1 = *(const float2*)&h[(size_t)(r + 1) * DH + t * 2];
        a0.x += v0.x; a0.y += v0.y;
        a1.x += v1.x; a1.y += v1.y;
    }
    if (r < end) {
        float2 v = *(const float2*)&h[(size_t)r * DH + t * 2];
        a0.x += v.x; a0.y += v.y;
    }
    float inv = 1.0f / fmaxf((float)(end - start), 1.0f);
    *(float2*)&g_pooled[enc][g * DH + t * 2] =
        make_float2((a0.x + a1.x) * inv, (a0.y + a1.y) * inv);
}

__device__ void dist_phase(float* __restrict__ out, float* sred) {
    int g = blockIdx.x;
    if (g >= GG) return;
    int t = threadIdx.x;

    float2 a = *(const float2*)&g_pooled[0][g * DH + t * 2];
    float2 b = *(const float2*)&g_pooled[1][g * DH + t * 2];
    float dx = a.x - b.x + 1e-6f;
    float dy = a.y - b.y + 1e-6f;
    float s = dx * dx + dy * dy;

    sred[t] = s;
    __syncthreads();
    for (int off = 128; off > 0; off >>= 1) {
        if (t < off) sred[t] += sred[t + off];
        __syncthreads();
    }
    if (t == 0) out[g] = sqrtf(sred[0]);
}

// ---- mega kernel --------------------------------------------------------------
extern __shared__ __align__(16) unsigned char smem_dyn[];

__global__ __launch_bounds__(TPB, 1) void mega_kernel(
    const float* __restrict__ x_a, const int* __restrict__ ei_a,
    const int* __restrict__ batch_a,
    const float* __restrict__ x_b, const int* __restrict__ ei_b,
    const int* __restrict__ batch_b,
    const float* __restrict__ W1, const float* __restrict__ b1,
    const float* __restrict__ W2, const float* __restrict__ b2,
    const float* __restrict__ W3, const float* __restrict__ b3,
    float* __restrict__ out)
{
    unsigned char* sm = smem_dyn;
    const int tid = threadIdx.x, bid = blockIdx.x;
    unsigned target = *((volatile unsigned*)&g_gen);

    // ---- weight transpose + split (once; shared by both encoders) ----
    {
        const float* Ws[3] = {W1, W2, W3};
        const int total = 3 * DH * DH;
        for (int idx = bid * TPB + tid; idx < total; idx += NB * TPB) {
            int l = idx >> 18;
            int rem = idx & (DH * DH - 1);
            int k = rem >> 9;
            int n = rem & 511;          // fastest -> coalesced W reads
            float w = Ws[l][k * DH + n];
            __nv_bfloat16 h, lo;
            bf_split(w, h, lo);
            g_wthi[l * DH * DH + n * DH + k] = h;
            g_wtlo[l * DH * DH + n * DH + k] = lo;
        }
    }
    gsync(++target);

    for (int enc = 0; enc < 2; enc++) {
        const float* x   = enc ? x_b : x_a;
        const int* srcv  = enc ? ei_b : ei_a;
        const int* dstv  = srcv + EE;
        const int* batch = enc ? batch_b : batch_a;

        // ---- count degrees ----
        for (int e = bid * TPB + tid; e < EE; e += NB * TPB)
            atomicAdd(&g_deg[dstv[e]], 1);
        gsync(++target);

        // ---- block 0: scan; blocks 1..: split x into bf16 hi/lo ----
        if (bid == 0) {
            int* sh = (int*)(sm + SM_RED);
            const int chunk = (NN + TPB - 1) / TPB;   // 79
            int base = tid * chunk;
            int local = 0;
            for (int j = 0; j < chunk; j++) {
                int idx = base + j;
                if (idx < NN) local += g_deg[idx];
            }
            sh[tid] = local;
            __syncthreads();
            for (int off = 1; off < TPB; off <<= 1) {
                int v = (tid >= off) ? sh[tid - off] : 0;
                __syncthreads();
                sh[tid] += v;
                __syncthreads();
            }
            int run = tid ? sh[tid - 1] : 0;
            for (int j = 0; j < chunk; j++) {
                int idx = base + j;
                if (idx < NN) {
                    int d = g_deg[idx];
                    g_deg[idx]    = 0;               // restore invariant
                    g_rowptr[idx] = run;
                    g_cursor[idx] = run;
                    g_dinv[idx]   = rsqrtf((float)d + 1.0f);
                    run += d;
                }
            }
            if (tid == TPB - 1) g_rowptr[NN] = sh[TPB - 1];
        } else {
            const int total4 = NN * DH / 4;
            for (int idx = (bid - 1) * TPB + tid; idx < total4; idx += (NB - 1) * TPB) {
                float4 v = *(const float4*)(x + (size_t)idx * 4);
                __nv_bfloat162 h01, h23, l01, l23;
                bf_split(v.x, h01.x, l01.x); bf_split(v.y, h01.y, l01.y);
                bf_split(v.z, h23.x, l23.x); bf_split(v.w, h23.y, l23.y);
                __nv_bfloat162* hp = (__nv_bfloat162*)(g_ahi + (size_t)idx * 4);
                __nv_bfloat162* lp = (__nv_bfloat162*)(g_alo + (size_t)idx * 4);
                hp[0] = h01; hp[1] = h23;
                lp[0] = l01; lp[1] = l23;
            }
        }
        gsync(++target);

        // ---- fill CSR ----
        for (int e = bid * TPB + tid; e < EE; e += NB * TPB) {
            int s = srcv[e], d = dstv[e];
            int pos = atomicAdd(&g_cursor[d], 1);
            g_csr_src[pos]  = s;
            g_csr_norm[pos] = g_dinv[s] * g_dinv[d];
        }
        gsync(++target);

        // ---- 3 GCN layers ----
        for (int l = 0; l < 3; l++) {
            const float* bb = (l == 0) ? b1 : (l == 1) ? b2 : b3;
            gemm_phase(sm, g_wthi + l * DH * DH, g_wtlo + l * DH * DH, g_gemm);
            gsync(++target);
            agg_phase(g_gemm, bb, l);   // l<2 writes bf16 hi/lo; l==2 writes g_x
            gsync(++target);
        }

        // ---- mean pool ----
        pool_phase(g_x, batch, enc);
        gsync(++target);
    }

    // ---- pairwise distance ----
    dist_phase(out, (float*)(sm + SM_RED));
}

// ---------------------------------------------------------------------------
// launch: ONE kernel (dynamic smem ~83KB)
// ---------------------------------------------------------------------------
extern "C" void kernel_launch(void* const* d_in, const int* in_sizes, int n_in,
                              void* d_out, int out_size) {
    const float* x_a     = (const float*)d_in[0];
    const int*   ei_a    = (const int*)  d_in[1];
    const int*   batch_a = (const int*)  d_in[2];
    const float* x_b     = (const float*)d_in[3];
    const int*   ei_b    = (const int*)  d_in[4];
    const int*   batch_b = (const int*)  d_in[5];
    const float* W1 = (const float*)d_in[6];
    const float* b1 = (const float*)d_in[7];
    const float* W2 = (const float*)d_in[8];
    const float* b2 = (const float*)d_in[9];
    const float* W3 = (const float*)d_in[10];
    const float* b3 = (const float*)d_in[11];
    float* out = (float*)d_out;

    cudaFuncSetAttribute(mega_kernel, cudaFuncAttributeMaxDynamicSharedMemorySize,
                         SMEM_BYTES);
    mega_kernel<<<NB, TPB, SMEM_BYTES>>>(x_a, ei_a, batch_a, x_b, ei_b, batch_b,
                                         W1, b1, W2, b2, W3, b3, out);
}

// round 8
// speedup vs baseline: 22.7141x; 1.1720x over previous
#include <cuda_runtime.h>
#include <cuda_bf16.h>
#include <cstdint>

// ---------------------------------------------------------------------------
// SiameseBrainNet: persistent mega-kernel + mma.sync split-bf16 GEMM
// R8: ldmatrix fragments + cp.async double-buffered k-chunks, agg unroll 8
// ---------------------------------------------------------------------------

#define NN 20000
#define EE 640000
#define DH 512
#define GG 64
#define NB 148
#define TPB 256
#define MT 157
#define NTILE (4 * MT)        // 628 output tiles (128x128)

#define KSTR 72               // bf16 elements per smem row (64 data + 8 pad)
#define TILE_BYTES (128 * KSTR * 2)          // 18432
#define BUF_BYTES  (4 * TILE_BYTES)          // 73728 (Ahi,Alo,Bhi,Blo)
#define SM_RED     (2 * BUF_BYTES)           // 147456
#define SMEM_BYTES (SM_RED + 1024)           // 148480

// ---- scratch ---------------------------------------------------------------
__device__ float g_gemm[NN * DH];
__device__ float g_x[NN * DH];
__device__ __nv_bfloat16 g_ahi[NN * DH];
__device__ __nv_bfloat16 g_alo[NN * DH];
__device__ __nv_bfloat16 g_wthi[3 * DH * DH];   // W^T split, [l][n][k]
__device__ __nv_bfloat16 g_wtlo[3 * DH * DH];
__device__ int   g_deg[NN];        // INVARIANT: zero at kernel entry
__device__ int   g_rowptr[NN + 1];
__device__ int   g_cursor[NN];
__device__ float g_dinv[NN];
__device__ int   g_csr_src[EE];
__device__ float g_csr_norm[EE];
__device__ float g_pooled[2][GG * DH];
__device__ unsigned g_count, g_gen;

// ---- grid barrier -----------------------------------------------------------
__device__ __forceinline__ void gsync(unsigned target) {
    __syncthreads();
    if (threadIdx.x == 0) {
        __threadfence();
        if (atomicAdd(&g_count, 1u) == NB - 1u) {
            atomicExch(&g_count, 0u);
            __threadfence();
            atomicAdd(&g_gen, 1u);
        } else {
            while (*((volatile unsigned*)&g_gen) < target) __nanosleep(64);
        }
        __threadfence();
    }
    __syncthreads();
}

// ---- tensor-core primitives ---------------------------------------------------
__device__ __forceinline__ void mma16816(float* d,
                                         uint32_t a0, uint32_t a1, uint32_t a2, uint32_t a3,
                                         uint32_t b0, uint32_t b1) {
    asm volatile(
        "mma.sync.aligned.m16n8k16.row.col.f32.bf16.bf16.f32 "
        "{%0,%1,%2,%3}, {%4,%5,%6,%7}, {%8,%9}, {%0,%1,%2,%3};"
        : "+f"(d[0]), "+f"(d[1]), "+f"(d[2]), "+f"(d[3])
        : "r"(a0), "r"(a1), "r"(a2), "r"(a3), "r"(b0), "r"(b1));
}
__device__ __forceinline__ void ldsm4(uint32_t& r0, uint32_t& r1, uint32_t& r2, uint32_t& r3,
                                      uint32_t addr) {
    asm volatile("ldmatrix.sync.aligned.m8n8.x4.shared.b16 {%0,%1,%2,%3}, [%4];"
                 : "=r"(r0), "=r"(r1), "=r"(r2), "=r"(r3) : "r"(addr));
}
#define CP_COMMIT() asm volatile("cp.async.commit_group;" ::: "memory")
#define CP_WAIT(n)  asm volatile("cp.async.wait_group %0;" :: "n"(n) : "memory")

// async fill: gmem bf16 [.,512] -> smem tile 128x64 (stride KSTR)
__device__ __forceinline__ void fill_tile_async(uint32_t smt,
                                                const __nv_bfloat16* __restrict__ g,
                                                int row0, int kc, int nrows) {
    const int tid = threadIdx.x;
#pragma unroll
    for (int i = 0; i < 4; i++) {
        int idx = i * 256 + tid;       // 0..1023
        int r   = idx >> 3;            // 0..127
        int c8  = (idx & 7) << 3;      // 0..56
        int gr  = row0 + r;
        bool valid = (gr < nrows);
        const void* src = g + (size_t)(valid ? gr : 0) * DH + kc + c8;
        uint32_t dst = smt + (uint32_t)(r * KSTR + c8) * 2;
        int sz = valid ? 16 : 0;
        asm volatile("cp.async.cg.shared.global [%0], [%1], 16, %2;"
                     :: "r"(dst), "l"(src), "r"(sz) : "memory");
    }
}

// ---- GEMM phase: C[NN,512] = A @ W, split-bf16 x3, fp32 accum ----------------
__device__ void gemm_phase(uint32_t smb,
                           const __nv_bfloat16* __restrict__ Whi,
                           const __nv_bfloat16* __restrict__ Wlo,
                           float* __restrict__ C) {
    const int tid  = threadIdx.x;
    const int lane = tid & 31, warp = tid >> 5;
    const int wm = warp & 3;        // 32-row group
    const int wn = warp >> 2;       // 64-col group
    const int g  = lane >> 2;       // epilogue row-in-8
    const int tg = lane & 3;        // epilogue col pair
    const int seg = lane >> 3;      // ldmatrix segment 0..3
    const int lr  = lane & 7;

    // per-thread ldmatrix element offsets within a tile (elements)
    // A(mt): row = wm*32 + mt*16 + (seg&1)*8 + lr ; col += (seg>>1)*8
    const int aoff0 = (wm * 32 + 0  + (seg & 1) * 8 + lr) * KSTR + (seg >> 1) * 8;
    const int aoff1 = (wm * 32 + 16 + (seg & 1) * 8 + lr) * KSTR + (seg >> 1) * 8;
    // B(nq): row = wn*64 + nq*16 + (seg&1)*8 + lr
    const int boffb = (wn * 64 + (seg & 1) * 8 + lr) * KSTR + (seg >> 1) * 8;

    for (int t = blockIdx.x; t < NTILE; t += NB) {
        const int bm = t >> 2, bn = t & 3;

        float acc[2][8][4];
#pragma unroll
        for (int mt = 0; mt < 2; mt++)
#pragma unroll
            for (int nt = 0; nt < 8; nt++)
#pragma unroll
                for (int q = 0; q < 4; q++) acc[mt][nt][q] = 0.0f;

        // prologue: fill k-chunk 0 into buffer 0
        fill_tile_async(smb + 0 * TILE_BYTES, g_ahi, bm * 128, 0, NN);
        fill_tile_async(smb + 1 * TILE_BYTES, g_alo, bm * 128, 0, NN);
        fill_tile_async(smb + 2 * TILE_BYTES, Whi,   bn * 128, 0, 1 << 30);
        fill_tile_async(smb + 3 * TILE_BYTES, Wlo,   bn * 128, 0, 1 << 30);
        CP_COMMIT();

#pragma unroll 1
        for (int kc8 = 0; kc8 < 8; kc8++) {
            const uint32_t cur = smb + (uint32_t)(kc8 & 1) * BUF_BYTES;
            if (kc8 + 1 < 8) {
                const uint32_t nxt = smb + (uint32_t)((kc8 + 1) & 1) * BUF_BYTES;
                fill_tile_async(nxt + 0 * TILE_BYTES, g_ahi, bm * 128, (kc8 + 1) * 64, NN);
                fill_tile_async(nxt + 1 * TILE_BYTES, g_alo, bm * 128, (kc8 + 1) * 64, NN);
                fill_tile_async(nxt + 2 * TILE_BYTES, Whi,   bn * 128, (kc8 + 1) * 64, 1 << 30);
                fill_tile_async(nxt + 3 * TILE_BYTES, Wlo,   bn * 128, (kc8 + 1) * 64, 1 << 30);
                CP_COMMIT();
                CP_WAIT(1);
            } else {
                CP_WAIT(0);
            }
            __syncthreads();

            const uint32_t Ahi = cur + 0 * TILE_BYTES;
            const uint32_t Alo = cur + 1 * TILE_BYTES;
            const uint32_t Bhi = cur + 2 * TILE_BYTES;
            const uint32_t Blo = cur + 3 * TILE_BYTES;

#pragma unroll
            for (int ks4 = 0; ks4 < 4; ks4++) {
                const uint32_t kb = (uint32_t)(ks4 * 16) * 2;   // bytes

                // B fragments: 4 x ldsm4 per precision, covering n 0..63
                uint32_t bh[8][2], bl[8][2];
#pragma unroll
                for (int nq = 0; nq < 4; nq++) {
                    uint32_t r0, r1, r2, r3;
                    ldsm4(r0, r1, r2, r3, Bhi + (uint32_t)(boffb + nq * 16 * KSTR) * 2 + kb);
                    bh[nq * 2][0] = r0; bh[nq * 2 + 1][0] = r1;
                    bh[nq * 2][1] = r2; bh[nq * 2 + 1][1] = r3;
                    ldsm4(r0, r1, r2, r3, Blo + (uint32_t)(boffb + nq * 16 * KSTR) * 2 + kb);
                    bl[nq * 2][0] = r0; bl[nq * 2 + 1][0] = r1;
                    bl[nq * 2][1] = r2; bl[nq * 2 + 1][1] = r3;
                }
#pragma unroll
                for (int mt = 0; mt < 2; mt++) {
                    const int aoff = mt ? aoff1 : aoff0;
                    uint32_t ah0, ah1, ah2, ah3, al0, al1, al2, al3;
                    ldsm4(ah0, ah1, ah2, ah3, Ahi + (uint32_t)aoff * 2 + kb);
                    ldsm4(al0, al1, al2, al3, Alo + (uint32_t)aoff * 2 + kb);
#pragma unroll
                    for (int nt = 0; nt < 8; nt++) {
                        mma16816(acc[mt][nt], ah0, ah1, ah2, ah3, bh[nt][0], bh[nt][1]);
                        mma16816(acc[mt][nt], al0, al1, al2, al3, bh[nt][0], bh[nt][1]);
                        mma16816(acc[mt][nt], ah0, ah1, ah2, ah3, bl[nt][0], bl[nt][1]);
                    }
                }
            }
            __syncthreads();
        }

        // epilogue: D(16x8) frag -> c0,c1 at (g, 2tg), c2,c3 at (g+8, 2tg)
#pragma unroll
        for (int mt = 0; mt < 2; mt++) {
            int row0 = bm * 128 + wm * 32 + mt * 16 + g;
#pragma unroll
            for (int nt = 0; nt < 8; nt++) {
                int col = bn * 128 + wn * 64 + nt * 8 + 2 * tg;
                if (row0 < NN)
                    *(float2*)&C[(size_t)row0 * DH + col] =
                        make_float2(acc[mt][nt][0], acc[mt][nt][1]);
                if (row0 + 8 < NN)
                    *(float2*)&C[(size_t)(row0 + 8) * DH + col] =
                        make_float2(acc[mt][nt][2], acc[mt][nt][3]);
            }
        }
        __syncthreads();
    }
}

// ---- aggregation (fused bf16 split for layers 0,1) --------------------------
__device__ __forceinline__ void bf_split(float v, __nv_bfloat16& h, __nv_bfloat16& l) {
    h = __float2bfloat16(v);
    l = __float2bfloat16(v - __bfloat162float(h));
}

__device__ void agg_phase(const float* __restrict__ h, const float* __restrict__ bias, int l) {
    const int sub = threadIdx.x >> 7;
    const int t   = threadIdx.x & 127;
    const float4 b4 = *(const float4*)&bias[t * 4];

    for (int i = blockIdx.x * 2 + sub; i < NN; i += NB * 2) {
        int r0 = g_rowptr[i];
        int r1 = g_rowptr[i + 1];

        float4 a0 = make_float4(0.f, 0.f, 0.f, 0.f);
        float4 a1 = a0, a2 = a0, a3 = a0;

        int e = r0;
        for (; e + 7 < r1; e += 8) {
            int   s0 = g_csr_src[e],     s1 = g_csr_src[e + 1];
            int   s2 = g_csr_src[e + 2], s3 = g_csr_src[e + 3];
            int   s4 = g_csr_src[e + 4], s5 = g_csr_src[e + 5];
            int   s6 = g_csr_src[e + 6], s7 = g_csr_src[e + 7];
            float w0 = g_csr_norm[e],     w1 = g_csr_norm[e + 1];
            float w2 = g_csr_norm[e + 2], w3 = g_csr_norm[e + 3];
            float w4 = g_csr_norm[e + 4], w5 = g_csr_norm[e + 5];
            float w6 = g_csr_norm[e + 6], w7 = g_csr_norm[e + 7];
            float4 v0 = *(const float4*)&h[(size_t)s0 * DH + t * 4];
            float4 v1 = *(const float4*)&h[(size_t)s1 * DH + t * 4];
            float4 v2 = *(const float4*)&h[(size_t)s2 * DH + t * 4];
            float4 v3 = *(const float4*)&h[(size_t)s3 * DH + t * 4];
            float4 v4 = *(const float4*)&h[(size_t)s4 * DH + t * 4];
            float4 v5 = *(const float4*)&h[(size_t)s5 * DH + t * 4];
            float4 v6 = *(const float4*)&h[(size_t)s6 * DH + t * 4];
            float4 v7 = *(const float4*)&h[(size_t)s7 * DH + t * 4];
            a0.x += w0 * v0.x; a0.y += w0 * v0.y; a0.z += w0 * v0.z; a0.w += w0 * v0.w;
            a1.x += w1 * v1.x; a1.y += w1 * v1.y; a1.z += w1 * v1.z; a1.w += w1 * v1.w;
            a2.x += w2 * v2.x; a2.y += w2 * v2.y; a2.z += w2 * v2.z; a2.w += w2 * v2.w;
            a3.x += w3 * v3.x; a3.y += w3 * v3.y; a3.z += w3 * v3.z; a3.w += w3 * v3.w;
            a0.x += w4 * v4.x; a0.y += w4 * v4.y; a0.z += w4 * v4.z; a0.w += w4 * v4.w;
            a1.x += w5 * v5.x; a1.y += w5 * v5.y; a1.z += w5 * v5.z; a1.w += w5 * v5.w;
            a2.x += w6 * v6.x; a2.y += w6 * v6.y; a2.z += w6 * v6.z; a2.w += w6 * v6.w;
            a3.x += w7 * v7.x; a3.y += w7 * v7.y; a3.z += w7 * v7.z; a3.w += w7 * v7.w;
        }
        for (; e < r1; e++) {
            int   s = g_csr_src[e];
            float w = g_csr_norm[e];
            float4 v = *(const float4*)&h[(size_t)s * DH + t * 4];
            a0.x += w * v.x; a0.y += w * v.y; a0.z += w * v.z; a0.w += w * v.w;
        }

        float4 acc;
        acc.x = (a0.x + a1.x) + (a2.x + a3.x);
        acc.y = (a0.y + a1.y) + (a2.y + a3.y);
        acc.z = (a0.z + a1.z) + (a2.z + a3.z);
        acc.w = (a0.w + a1.w) + (a2.w + a3.w);

        float d = g_dinv[i];
        float wd = d * d;
        float4 vs = *(const float4*)&h[(size_t)i * DH + t * 4];
        acc.x += wd * vs.x + b4.x;
        acc.y += wd * vs.y + b4.y;
        acc.z += wd * vs.z + b4.z;
        acc.w += wd * vs.w + b4.w;

        if (l < 2) {
            acc.x = fmaxf(acc.x, 0.f); acc.y = fmaxf(acc.y, 0.f);
            acc.z = fmaxf(acc.z, 0.f); acc.w = fmaxf(acc.w, 0.f);
            __nv_bfloat162 h01, h23, l01, l23;
            bf_split(acc.x, h01.x, l01.x); bf_split(acc.y, h01.y, l01.y);
            bf_split(acc.z, h23.x, l23.x); bf_split(acc.w, h23.y, l23.y);
            __nv_bfloat162* hp = (__nv_bfloat162*)(g_ahi + (size_t)i * DH + t * 4);
            __nv_bfloat162* lp = (__nv_bfloat162*)(g_alo + (size_t)i * DH + t * 4);
            hp[0] = h01; hp[1] = h23;
            lp[0] = l01; lp[1] = l23;
        } else {
            *(float4*)&g_x[(size_t)i * DH + t * 4] = acc;
        }
    }
}

// ---- pool / dist -------------------------------------------------------------
__device__ void pool_phase(const float* __restrict__ h, const int* __restrict__ batch, int enc) {
    int g = blockIdx.x;
    if (g >= GG) return;
    int t = threadIdx.x;

    int lo = 0, hi = NN;
    while (lo < hi) { int m = (lo + hi) >> 1; if (batch[m] < g) lo = m + 1; else hi = m; }
    int start = lo;
    lo = start; hi = NN;
    while (lo < hi) { int m = (lo + hi) >> 1; if (batch[m] < g + 1) lo = m + 1; else hi = m; }
    int end = lo;

    float2 a0 = make_float2(0.f, 0.f), a1 = a0;
    int r = start;
    for (; r + 1 < end; r += 2) {
        float2 v0 = *(const float2*)&h[(size_t)r * DH + t * 2];
        float2 v1 = *(const float2*)&h[(size_t)(r + 1) * DH + t * 2];
        a0.x += v0.x; a0.y += v0.y;
        a1.x += v1.x; a1.y += v1.y;
    }
    if (r < end) {
        float2 v = *(const float2*)&h[(size_t)r * DH + t * 2];
        a0.x += v.x; a0.y += v.y;
    }
    float inv = 1.0f / fmaxf((float)(end - start), 1.0f);
    *(float2*)&g_pooled[enc][g * DH + t * 2] =
        make_float2((a0.x + a1.x) * inv, (a0.y + a1.y) * inv);
}

__device__ void dist_phase(float* __restrict__ out, float* sred) {
    int g = blockIdx.x;
    if (g >= GG) return;
    int t = threadIdx.x;

    float2 a = *(const float2*)&g_pooled[0][g * DH + t * 2];
    float2 b = *(const float2*)&g_pooled[1][g * DH + t * 2];
    float dx = a.x - b.x + 1e-6f;
    float dy = a.y - b.y + 1e-6f;
    float s = dx * dx + dy * dy;

    sred[t] = s;
    __syncthreads();
    for (int off = 128; off > 0; off >>= 1) {
        if (t < off) sred[t] += sred[t + off];
        __syncthreads();
    }
    if (t == 0) out[g] = sqrtf(sred[0]);
}

// ---- mega kernel --------------------------------------------------------------
extern __shared__ __align__(16) unsigned char smem_dyn[];

__global__ __launch_bounds__(TPB, 1) void mega_kernel(
    const float* __restrict__ x_a, const int* __restrict__ ei_a,
    const int* __restrict__ batch_a,
    const float* __restrict__ x_b, const int* __restrict__ ei_b,
    const int* __restrict__ batch_b,
    const float* __restrict__ W1, const float* __restrict__ b1,
    const float* __restrict__ W2, const float* __restrict__ b2,
    const float* __restrict__ W3, const float* __restrict__ b3,
    float* __restrict__ out)
{
    unsigned char* sm = smem_dyn;
    const uint32_t smb = (uint32_t)__cvta_generic_to_shared(sm);
    const int tid = threadIdx.x, bid = blockIdx.x;
    unsigned target = *((volatile unsigned*)&g_gen);

    // ---- weight transpose + split (once; shared by both encoders) ----
    {
        const float* Ws[3] = {W1, W2, W3};
        const int total = 3 * DH * DH;
        for (int idx = bid * TPB + tid; idx < total; idx += NB * TPB) {
            int l = idx >> 18;
            int rem = idx & (DH * DH - 1);
            int k = rem >> 9;
            int n = rem & 511;
            float w = Ws[l][k * DH + n];
            __nv_bfloat16 h, lo;
            bf_split(w, h, lo);
            g_wthi[l * DH * DH + n * DH + k] = h;
            g_wtlo[l * DH * DH + n * DH + k] = lo;
        }
    }
    gsync(++target);

    for (int enc = 0; enc < 2; enc++) {
        const float* x   = enc ? x_b : x_a;
        const int* srcv  = enc ? ei_b : ei_a;
        const int* dstv  = srcv + EE;
        const int* batch = enc ? batch_b : batch_a;

        // ---- count degrees ----
        for (int e = bid * TPB + tid; e < EE; e += NB * TPB)
            atomicAdd(&g_deg[dstv[e]], 1);
        gsync(++target);

        // ---- block 0: scan; blocks 1..: split x into bf16 hi/lo ----
        if (bid == 0) {
            int* sh = (int*)(sm + SM_RED);
            const int chunk = (NN + TPB - 1) / TPB;   // 79
            int base = tid * chunk;
            int local = 0;
            for (int j = 0; j < chunk; j++) {
                int idx = base + j;
                if (idx < NN) local += g_deg[idx];
            }
            sh[tid] = local;
            __syncthreads();
            for (int off = 1; off < TPB; off <<= 1) {
                int v = (tid >= off) ? sh[tid - off] : 0;
                __syncthreads();
                sh[tid] += v;
                __syncthreads();
            }
            int run = tid ? sh[tid - 1] : 0;
            for (int j = 0; j < chunk; j++) {
                int idx = base + j;
                if (idx < NN) {
                    int d = g_deg[idx];
                    g_deg[idx]    = 0;
                    g_rowptr[idx] = run;
                    g_cursor[idx] = run;
                    g_dinv[idx]   = rsqrtf((float)d + 1.0f);
                    run += d;
                }
            }
            if (tid == TPB - 1) g_rowptr[NN] = sh[TPB - 1];
        } else {
            const int total4 = NN * DH / 4;
            for (int idx = (bid - 1) * TPB + tid; idx < total4; idx += (NB - 1) * TPB) {
                float4 v = *(const float4*)(x + (size_t)idx * 4);
                __nv_bfloat162 h01, h23, l01, l23;
                bf_split(v.x, h01.x, l01.x); bf_split(v.y, h01.y, l01.y);
                bf_split(v.z, h23.x, l23.x); bf_split(v.w, h23.y, l23.y);
                __nv_bfloat162* hp = (__nv_bfloat162*)(g_ahi + (size_t)idx * 4);
                __nv_bfloat162* lp = (__nv_bfloat162*)(g_alo + (size_t)idx * 4);
                hp[0] = h01; hp[1] = h23;
                lp[0] = l01; lp[1] = l23;
            }
        }
        gsync(++target);

        // ---- fill CSR ----
        for (int e = bid * TPB + tid; e < EE; e += NB * TPB) {
            int s = srcv[e], d = dstv[e];
            int pos = atomicAdd(&g_cursor[d], 1);
            g_csr_src[pos]  = s;
            g_csr_norm[pos] = g_dinv[s] * g_dinv[d];
        }
        gsync(++target);

        // ---- 3 GCN layers ----
        for (int l = 0; l < 3; l++) {
            const float* bb = (l == 0) ? b1 : (l == 1) ? b2 : b3;
            gemm_phase(smb, g_wthi + l * DH * DH, g_wtlo + l * DH * DH, g_gemm);
            gsync(++target);
            agg_phase(g_gemm, bb, l);
            gsync(++target);
        }

        // ---- mean pool ----
        pool_phase(g_x, batch, enc);
        gsync(++target);
    }

    // ---- pairwise distance ----
    dist_phase(out, (float*)(sm + SM_RED));
}

// ---------------------------------------------------------------------------
// launch: ONE kernel (dynamic smem ~145KB)
// ---------------------------------------------------------------------------
extern "C" void kernel_launch(void* const* d_in, const int* in_sizes, int n_in,
                              void* d_out, int out_size) {
    const float* x_a     = (const float*)d_in[0];
    const int*   ei_a    = (const int*)  d_in[1];
    const int*   batch_a = (const int*)  d_in[2];
    const float* x_b     = (const float*)d_in[3];
    const int*   ei_b    = (const int*)  d_in[4];
    const int*   batch_b = (const int*)  d_in[5];
    const float* W1 = (const float*)d_in[6];
    const float* b1 = (const float*)d_in[7];
    const float* W2 = (const float*)d_in[8];
    const float* b2 = (const float*)d_in[9];
    const float* W3 = (const float*)d_in[10];
    const float* b3 = (const float*)d_in[11];
    float* out = (float*)d_out;

    cudaFuncSetAttribute(mega_kernel, cudaFuncAttributeMaxDynamicSharedMemorySize,
                         SMEM_BYTES);
    mega_kernel<<<NB, TPB, SMEM_BYTES>>>(x_a, ei_a, batch_a, x_b, ei_b, batch_b,
                                         W1, b1, W2, b2, W3, b3, out);
}